// round 11
// baseline (speedup 1.0000x reference)
#include <cuda_runtime.h>

// Problem constants (fixed shapes per reference: B=128, C=1, H=W=512, BINS=256)
#define NBINS      256
#define HEIGHT_RT  0.05f
#define NB         128                 // batch
#define NPER       262144              // 512*512 elems per sample
#define CHUNKS     8                   // hist blocks per sample
#define CHUNK_EL   (NPER / CHUNKS)     // 32768 elems per hist block
#define OUT_X      ((size_t)NB * NPER) // big output, then NB values
#define GS         32                  // samples per pipeline group (33.5 MB)
#define NG         (NB / GS)           // 4 groups
#define HB         (GS * CHUNKS)       // 256 hist blocks per group
#define SB         (GS * 64)           // 2048 scale tiles per group (SB == 8*HB)

// Scratch (no allocations). Every slot fully overwritten each call.
__device__ unsigned int g_hist_partial[NB * CHUNKS * NBINS];   // 1 MB
__device__ float        g_w[NB];

// ===========================================================================
// Role bodies (block-uniform branches; each may use __syncthreads freely)
// ===========================================================================

__device__ __forceinline__ void hist_body(const float* __restrict__ x,
                                          int sample, int chunk,
                                          unsigned int (*sh)[NBINS])
{
    const int tid  = threadIdx.x;
    const int warp = tid >> 5;

    #pragma unroll
    for (int c = 0; c < 8; c++) sh[c][tid] = 0u;
    __syncthreads();

    const float4* __restrict__ p =
        (const float4*)(x + (size_t)sample * NPER + (size_t)chunk * CHUNK_EL);
    #pragma unroll 8
    for (int j = 0; j < 32; j++) {
        float4 v = p[j * 256 + tid];
        float vals[4] = {v.x, v.y, v.z, v.w};
        #pragma unroll
        for (int k = 0; k < 4; k++) {
            float f = vals[k];
            if (f >= 0.0f && f <= 1.0f) {        // torch.histc: out-of-range ignored
                int b = (int)(f * 256.0f);       // floor (f >= 0)
                if (b > 255) b = 255;            // f == 1.0 -> last bin
                atomicAdd(&sh[warp][b], 1u);
            }
        }
    }
    __syncthreads();

    unsigned int s = 0;
    #pragma unroll
    for (int c = 0; c < 8; c++) s += sh[c][tid];
    g_hist_partial[((size_t)sample * CHUNKS + chunk) * NBINS + tid] = s;
}

__device__ __forceinline__ void scale_body(const float* __restrict__ x,
                                           float* __restrict__ out, int tile)
{
    const int sample = tile >> 6;                 // 64 tiles per sample
    const float w    = g_w[sample];

    const size_t base = (size_t)tile * 1024 + threadIdx.x;
    const float4* __restrict__ xin = (const float4*)x   + base;
    float4* __restrict__       o   = (float4*)out       + base;
    #pragma unroll
    for (int j = 0; j < 4; j++) {
        float4 v = __ldcs(xin + j * 256);         // last use: evict-first
        v.x *= w; v.y *= w; v.z *= w; v.w *= w;
        __stcs(o + j * 256, v);                   // streaming write
    }
}

__device__ __forceinline__ void mlp_body(
    const float* __restrict__ W1, const float* __restrict__ b1,
    const float* __restrict__ W2, const float* __restrict__ b2,
    const float* __restrict__ W3, const float* __restrict__ b3,
    const float* __restrict__ W4, const float* __restrict__ b4,
    float* __restrict__ out_value, int sample,
    unsigned int (*sh)[NBINS])
{
    // smem reuse (1 KB rows): row0 = float hist, row4 = scratch, rows 5-6 = MLP
    float*        s_h   = (float*)&sh[0][0];      // 256 floats
    unsigned int* s_red = &sh[4][0];              // 8 slots
    unsigned int* s_key = &sh[4][16];
    float*        s_l1p = (float*)&sh[5][0];      // 8*32
    float*        s_h1  = (float*)&sh[6][0];      // 32
    float*        s_h2  = (float*)&sh[6][32];     // 64
    float*        s_h3  = (float*)&sh[6][96];     // 128
    float*        s_p   = (float*)&sh[6][224];    // 4

    const int tid  = threadIdx.x;   // 0..255
    const int lane = tid & 31;
    const int warp = tid >> 5;

    unsigned int cnt;
    {
        unsigned int s = 0;
        const unsigned int* p = &g_hist_partial[(size_t)sample * CHUNKS * NBINS + tid];
        #pragma unroll
        for (int c = 0; c < CHUNKS; c++) s += p[c * NBINS];
        cnt = s;
        s_h[tid] = (float)s;
    }

    // First-occurrence argmax via packed key (count<<8)|(255-bin):
    // counts <= 262144 < 2^19 -> fits 27 bits; ties go to LOWEST index.
    unsigned int key = (cnt << 8) | (unsigned)(255 - tid);
    #pragma unroll
    for (int o = 16; o > 0; o >>= 1) {
        unsigned int other = __shfl_down_sync(0xffffffffu, key, o);
        if (other > key) key = other;
    }
    if (lane == 0) s_red[warp] = key;
    __syncthreads();
    if (tid == 0) {
        unsigned int k = s_red[0];
        #pragma unroll
        for (int i = 1; i < 8; i++) if (s_red[i] > k) k = s_red[i];
        *s_key = k;
    }
    __syncthreads();

    const int   am = 255 - (int)(*s_key & 255u);
    const float ch = (float)(*s_key >> 8) * HEIGHT_RT;
    __syncthreads();   // protect s_red reuse

    int mini = (tid >= am && !(s_h[tid] > ch)) ? tid : 0x7fffffff;
    #pragma unroll
    for (int o = 16; o > 0; o >>= 1) {
        int other = __shfl_down_sync(0xffffffffu, mini, o);
        if (other < mini) mini = other;
    }
    if (lane == 0) s_red[warp] = (unsigned)mini;
    __syncthreads();
    if (tid == 0) {
        int m = (int)s_red[0];
        #pragma unroll
        for (int i = 1; i < 8; i++) if ((int)s_red[i] < m) m = (int)s_red[i];
        if (m == 0x7fffffff) m = 0;
        out_value[sample] = (float)m / (float)NBINS;
    }

    // Layer 1: 256 -> 32  (8 partials x 32 outputs)
    {
        const int o = tid & 31, pp = tid >> 5;
        float acc = (pp == 0) ? b1[o] : 0.0f;
        const float* w = W1 + o * 256 + pp * 32;
        const float* h = s_h + pp * 32;
        #pragma unroll
        for (int k = 0; k < 32; k++) acc = fmaf(h[k], w[k], acc);
        s_l1p[pp * 32 + o] = acc;
    }
    __syncthreads();
    if (tid < 32) {
        float a = 0.0f;
        #pragma unroll
        for (int pp = 0; pp < 8; pp++) a += s_l1p[pp * 32 + tid];
        s_h1[tid] = fmaxf(a, 0.0f);
    }
    __syncthreads();

    if (tid < 64) {                               // Layer 2: 32 -> 64
        float acc = b2[tid];
        const float* w = W2 + tid * 32;
        #pragma unroll
        for (int k = 0; k < 32; k++) acc = fmaf(s_h1[k], w[k], acc);
        s_h2[tid] = fmaxf(acc, 0.0f);
    }
    __syncthreads();

    if (tid < 128) {                              // Layer 3: 64 -> 128
        float acc = b3[tid];
        const float* w = W3 + tid * 64;
        #pragma unroll
        for (int k = 0; k < 64; k++) acc = fmaf(s_h2[k], w[k], acc);
        s_h3[tid] = fmaxf(acc, 0.0f);
    }
    __syncthreads();

    float part = (tid < 128) ? s_h3[tid] * W4[tid] : 0.0f;   // Layer 4
    #pragma unroll
    for (int o = 16; o > 0; o >>= 1)
        part += __shfl_down_sync(0xffffffffu, part, o);
    if (lane == 0 && warp < 4) s_p[warp] = part;
    __syncthreads();
    if (tid == 0)
        g_w[sample] = s_p[0] + s_p[1] + s_p[2] + s_p[3] + b4[0];
}

// ===========================================================================
// Mixed kernel: block role decided by blockIdx. When both hist and scale are
// present they interleave 1:8 (SB == 8*HB) so every SM carries both traffic
// types. mlp blocks (if any) are the last (gridDim.x - nHist - nScale).
//   histS0/scaleS0/mlpS0: first sample (or tile group) of each role.
// ===========================================================================
__global__ __launch_bounds__(256) void mixed_kernel(
    const float* __restrict__ x,
    const float* __restrict__ W1, const float* __restrict__ b1,
    const float* __restrict__ W2, const float* __restrict__ b2,
    const float* __restrict__ W3, const float* __restrict__ b3,
    const float* __restrict__ W4, const float* __restrict__ b4,
    float* __restrict__ out, float* __restrict__ out_value,
    int histS0, int scaleS0, int mlpS0, int nHist, int nScale)
{
    __shared__ unsigned int sh[8][NBINS];         // hist copies / mlp scratch
    const int bid   = blockIdx.x;
    const int nMain = nHist + nScale;

    if (bid >= nMain) {
        // ---- mlp role ----
        mlp_body(W1, b1, W2, b2, W3, b3, W4, b4, out_value,
                 mlpS0 + (bid - nMain), sh);
        return;
    }
    if (nHist > 0 && nScale > 0) {
        // ---- interleaved 1:8 ----
        if (bid % 9 == 0) {
            const int u = bid / 9;                          // 0..nHist-1
            hist_body(x, histS0 + (u >> 3), u & 7, sh);
        } else {
            const int t = bid - bid / 9 - 1;                // 0..nScale-1
            scale_body(x, out, scaleS0 * 64 + t);
        }
    } else if (nHist > 0) {
        hist_body(x, histS0 + (bid >> 3), bid & 7, sh);
    } else {
        scale_body(x, out, scaleS0 * 64 + bid);
    }
}

// ---------------------------------------------------------------------------
extern "C" void kernel_launch(void* const* d_in, const int* in_sizes, int n_in,
                              void* d_out, int out_size)
{
    const float* x  = (const float*)d_in[0];
    const float* W1 = (const float*)d_in[1];
    const float* b1 = (const float*)d_in[2];
    const float* W2 = (const float*)d_in[3];
    const float* b2 = (const float*)d_in[4];
    const float* W3 = (const float*)d_in[5];
    const float* b3 = (const float*)d_in[6];
    const float* W4 = (const float*)d_in[7];
    const float* b4 = (const float*)d_in[8];

    float* out       = (float*)d_out;
    float* out_value = out + OUT_X;

    // Software pipeline over NG=4 groups, NG+2 launches:
    //   L_k : hist(g_k) || mlp(g_{k-1}) || scale(g_{k-2})
    // Launch boundaries provide all cross-phase ordering.
    for (int k = 0; k < NG + 2; k++) {
        const int hg = k;            // hist group
        const int mg = k - 1;        // mlp group
        const int sg = k - 2;        // scale group
        const int nHist  = (hg < NG) ? HB : 0;
        const int nScale = (sg >= 0) ? SB : 0;
        const int nMlp   = (mg >= 0 && mg < NG) ? GS : 0;
        const int grid   = nHist + nScale + nMlp;
        mixed_kernel<<<grid, 256>>>(x, W1, b1, W2, b2, W3, b3, W4, b4,
                                    out, out_value,
                                    (hg < NG) ? hg * GS : 0,
                                    (sg >= 0) ? sg * GS : 0,
                                    (nMlp > 0) ? mg * GS : 0,
                                    nHist, nScale);
    }
    (void)in_sizes; (void)n_in; (void)out_size;
}

// round 12
// speedup vs baseline: 1.7273x; 1.7273x over previous
#include <cuda_runtime.h>

// Problem constants (fixed shapes per reference: B=128, C=1, H=W=512, BINS=256)
#define NBINS      256
#define HEIGHT_RT  0.05f
#define NB         128                 // batch
#define NPER       262144              // 512*512 elems per sample
#define CHUNKS     8                   // hist blocks per sample
#define CHUNK_EL   (NPER / CHUNKS)     // 32768 elems per hist block
#define OUT_X      ((size_t)NB * NPER) // big output, then NB values
#define STILES     4096                // scale tiles of 2048 float4 (8192 elems)
#define TPS        32                  // scale tiles per sample

// Scratch (no allocations). Every slot fully overwritten each call.
__device__ unsigned int g_hist_partial[NB * CHUNKS * NBINS];   // 1 MB
__device__ float        g_w[NB];
__device__ volatile unsigned int g_ready[NB];   // reset by hist launch

// ---------------------------------------------------------------------------
// Kernel 1: per-(sample,chunk) histogram. grid = (CHUNKS, NB), 256 threads.
// Warp-private smem copies + atomics (measured ~26 us, DRAM 66%).
// chunk==0 blocks also reset the per-sample ready flags for this call
// (launch boundary orders this before the fused scale+mlp kernel).
// ---------------------------------------------------------------------------
__global__ __launch_bounds__(256) void hist_kernel(const float* __restrict__ x) {
    __shared__ unsigned int sh[8][NBINS];
    const int tid    = threadIdx.x;          // 0..255
    const int warp   = tid >> 5;
    const int sample = blockIdx.y;
    const int chunk  = blockIdx.x;

    if (chunk == 0 && tid == 0) g_ready[sample] = 0u;

    #pragma unroll
    for (int c = 0; c < 8; c++) sh[c][tid] = 0u;
    __syncthreads();

    const float4* __restrict__ p =
        (const float4*)(x + (size_t)sample * NPER + (size_t)chunk * CHUNK_EL);
    // 8192 float4 per block; 32 per thread
    #pragma unroll 8
    for (int j = 0; j < 32; j++) {
        float4 v = p[j * 256 + tid];
        float vals[4] = {v.x, v.y, v.z, v.w};
        #pragma unroll
        for (int k = 0; k < 4; k++) {
            float f = vals[k];
            if (f >= 0.0f && f <= 1.0f) {        // torch.histc: out-of-range ignored
                int b = (int)(f * 256.0f);       // floor (f >= 0)
                if (b > 255) b = 255;            // f == 1.0 -> last bin
                atomicAdd(&sh[warp][b], 1u);
            }
        }
    }
    __syncthreads();

    unsigned int s = 0;
    #pragma unroll
    for (int c = 0; c < 8; c++) s += sh[c][tid];
    g_hist_partial[((size_t)sample * CHUNKS + chunk) * NBINS + tid] = s;
}

// ---------------------------------------------------------------------------
// Kernel 2 (fused): blocks 0..NB-1 run value+MLP and publish g_w + flag;
// blocks NB.. run the scale pass, spin-waiting on their sample's flag.
// mlp blocks are the FIRST bids -> wave-1 resident -> no deadlock. Flag
// values are identical every call -> deterministic.
// ---------------------------------------------------------------------------
__global__ __launch_bounds__(256) void scale_mlp_kernel(
    const float* __restrict__ x,
    const float* __restrict__ W1, const float* __restrict__ b1,
    const float* __restrict__ W2, const float* __restrict__ b2,
    const float* __restrict__ W3, const float* __restrict__ b3,
    const float* __restrict__ W4, const float* __restrict__ b4,
    float* __restrict__ out, float* __restrict__ out_value)
{
    const int bid = blockIdx.x;
    const int tid = threadIdx.x;   // 0..255

    if (bid < NB) {
        // ============================ MLP role =============================
        __shared__ float        s_h[NBINS];
        __shared__ unsigned int s_red[8];
        __shared__ float        s_l1p[8][32];
        __shared__ float        s_h1[32];
        __shared__ float        s_h2[64];
        __shared__ float        s_h3[128];
        __shared__ float        s_p[4];
        __shared__ unsigned int s_key;

        const int b    = bid;
        const int lane = tid & 31;
        const int warp = tid >> 5;

        // Sum 8 chunk partials -> histogram (bin = tid)
        unsigned int cnt;
        {
            unsigned int s = 0;
            const unsigned int* p = &g_hist_partial[(size_t)b * CHUNKS * NBINS + tid];
            #pragma unroll
            for (int c = 0; c < CHUNKS; c++) s += p[c * NBINS];
            cnt = s;
            s_h[tid] = (float)s;
        }

        // First-occurrence argmax via packed key (count<<8)|(255-bin)
        unsigned int key = (cnt << 8) | (unsigned)(255 - tid);
        #pragma unroll
        for (int o = 16; o > 0; o >>= 1) {
            unsigned int other = __shfl_down_sync(0xffffffffu, key, o);
            if (other > key) key = other;
        }
        if (lane == 0) s_red[warp] = key;
        __syncthreads();
        if (tid == 0) {
            unsigned int k = s_red[0];
            #pragma unroll
            for (int i = 1; i < 8; i++) if (s_red[i] > k) k = s_red[i];
            s_key = k;
        }
        __syncthreads();

        const int   am = 255 - (int)(s_key & 255u);
        const float ch = (float)(s_key >> 8) * HEIGHT_RT;
        __syncthreads();   // protect s_red reuse

        int mini = (tid >= am && !(s_h[tid] > ch)) ? tid : 0x7fffffff;
        #pragma unroll
        for (int o = 16; o > 0; o >>= 1) {
            int other = __shfl_down_sync(0xffffffffu, mini, o);
            if (other < mini) mini = other;
        }
        if (lane == 0) s_red[warp] = (unsigned)mini;
        __syncthreads();
        if (tid == 0) {
            int m = (int)s_red[0];
            #pragma unroll
            for (int i = 1; i < 8; i++) if ((int)s_red[i] < m) m = (int)s_red[i];
            if (m == 0x7fffffff) m = 0;
            out_value[b] = (float)m / (float)NBINS;
        }

        // Layer 1: 256 -> 32  (8 partials x 32 outputs)
        {
            const int o = tid & 31, pp = tid >> 5;
            float acc = (pp == 0) ? b1[o] : 0.0f;
            const float* w = W1 + o * 256 + pp * 32;
            const float* h = s_h + pp * 32;
            #pragma unroll
            for (int k = 0; k < 32; k++) acc = fmaf(h[k], w[k], acc);
            s_l1p[pp][o] = acc;
        }
        __syncthreads();
        if (tid < 32) {
            float a = 0.0f;
            #pragma unroll
            for (int pp = 0; pp < 8; pp++) a += s_l1p[pp][tid];
            s_h1[tid] = fmaxf(a, 0.0f);
        }
        __syncthreads();

        if (tid < 64) {                           // Layer 2: 32 -> 64
            float acc = b2[tid];
            const float* w = W2 + tid * 32;
            #pragma unroll
            for (int k = 0; k < 32; k++) acc = fmaf(s_h1[k], w[k], acc);
            s_h2[tid] = fmaxf(acc, 0.0f);
        }
        __syncthreads();

        if (tid < 128) {                          // Layer 3: 64 -> 128
            float acc = b3[tid];
            const float* w = W3 + tid * 64;
            #pragma unroll
            for (int k = 0; k < 64; k++) acc = fmaf(s_h2[k], w[k], acc);
            s_h3[tid] = fmaxf(acc, 0.0f);
        }
        __syncthreads();

        float part = (tid < 128) ? s_h3[tid] * W4[tid] : 0.0f;   // Layer 4
        #pragma unroll
        for (int o = 16; o > 0; o >>= 1)
            part += __shfl_down_sync(0xffffffffu, part, o);
        if (lane == 0 && warp < 4) s_p[warp] = part;
        __syncthreads();
        if (tid == 0) {
            g_w[b] = s_p[0] + s_p[1] + s_p[2] + s_p[3] + b4[0];
            __threadfence();                      // publish w before flag
            g_ready[b] = 1u;                      // release
        }
        return;
    }

    // ============================ scale role ==============================
    const int tile   = bid - NB;                  // 0..STILES-1
    const int sample = tile >> 5;                 // TPS=32 tiles per sample
    __shared__ float s_w;

    if (tid == 0) {
        while (g_ready[sample] == 0u) __nanosleep(64);
        __threadfence();                          // acquire
        s_w = __ldcg(&g_w[sample]);               // L1-bypass: fresh value
    }
    __syncthreads();
    const float w = s_w;

    // 2048 float4 per block; 8 per thread, loads spread for MLP
    const size_t base = (size_t)sample * 65536 + (size_t)(tile & 31) * 2048 + tid;
    const float4* __restrict__ xin = (const float4*)x   + base;
    float4* __restrict__       o   = (float4*)out       + base;
    #pragma unroll
    for (int j = 0; j < 8; j++) {
        float4 v = xin[j * 256];                  // default caching
        v.x *= w; v.y *= w; v.z *= w; v.w *= w;
        __stcs(o + j * 256, v);                   // streaming write
    }
}

// ---------------------------------------------------------------------------
extern "C" void kernel_launch(void* const* d_in, const int* in_sizes, int n_in,
                              void* d_out, int out_size)
{
    const float* x  = (const float*)d_in[0];
    const float* W1 = (const float*)d_in[1];
    const float* b1 = (const float*)d_in[2];
    const float* W2 = (const float*)d_in[3];
    const float* b2 = (const float*)d_in[4];
    const float* W3 = (const float*)d_in[5];
    const float* b3 = (const float*)d_in[6];
    const float* W4 = (const float*)d_in[7];
    const float* b4 = (const float*)d_in[8];

    float* out       = (float*)d_out;
    float* out_value = out + OUT_X;

    dim3 hgrid(CHUNKS, NB);
    hist_kernel<<<hgrid, 256>>>(x);
    scale_mlp_kernel<<<NB + STILES, 256>>>(x, W1, b1, W2, b2, W3, b3, W4, b4,
                                           out, out_value);
    (void)in_sizes; (void)n_in; (void)out_size;
}